// round 7
// baseline (speedup 1.0000x reference)
#include <cuda_runtime.h>
#include <cuda_bf16.h>

#define D 256
#define NS 16
#define B_ROWS 131072
#define GRID_MAIN 148
#define TOTW_MAIN (GRID_MAIN * 8)
#define LN_EPS 1e-5f
#define ATT_EPS 1e-8f
#define SCALE 0.0625f

typedef unsigned long long ull;

// ---------------- device scratch (static; no runtime allocation) ----------------
__device__ float g_xln[(size_t)B_ROWS * D];   // LN(x) materialized once
__device__ float g_WkT[D * D];                // Wk transposed
__device__ float g_slots[NS * D];
__device__ float g_qk[NS * D];
__device__ float g_cn[NS];
__device__ float g_partU[GRID_MAIN * NS * D];
__device__ float g_partS[GRID_MAIN * NS];

// ---------------- helpers ----------------
__device__ __forceinline__ float warp_sum(float v) {
    v += __shfl_xor_sync(0xffffffffu, v, 16);
    v += __shfl_xor_sync(0xffffffffu, v, 8);
    v += __shfl_xor_sync(0xffffffffu, v, 4);
    v += __shfl_xor_sync(0xffffffffu, v, 2);
    v += __shfl_xor_sync(0xffffffffu, v, 1);
    return v;
}

// block-wide sum for blockDim.x == 1024 (threads without data must pass 0)
__device__ __forceinline__ float block_sum1024(float v, float* red) {
    const int lane = threadIdx.x & 31;
    const int w = threadIdx.x >> 5;
    v = warp_sum(v);
    if (lane == 0) red[w] = v;
    __syncthreads();
    if (w == 0) {
        float x = red[lane];
        x = warp_sum(x);
        if (lane == 0) red[0] = x;
    }
    __syncthreads();
    float r = red[0];
    __syncthreads();
    return r;
}

__device__ __forceinline__ float dot4(float4 a, float4 b) {
    return a.x * b.x + a.y * b.y + a.z * b.z + a.w * b.w;
}

__device__ __forceinline__ ull pack2(float lo, float hi) {
    ull r;
    asm("mov.b64 %0, {%1, %2};" : "=l"(r) : "f"(lo), "f"(hi));
    return r;
}
__device__ __forceinline__ void unpack2(ull v, float& lo, float& hi) {
    asm("mov.b64 {%0, %1}, %2;" : "=f"(lo), "=f"(hi) : "l"(v));
}
__device__ __forceinline__ void fma2(ull& d, ull a, ull b) {
    asm("fma.rn.f32x2 %0, %1, %2, %0;" : "+l"(d) : "l"(a), "l"(b));
}

__device__ __forceinline__ float sigmoidf_(float x) { return 1.0f / (1.0f + expf(-x)); }

// quad-split dot: thread (j = t>>2, kq = t&3) dots W[j, kq*64 .. +63] with in_s;
// quad-reduced result valid in all 4 lanes of the quad.
__device__ __forceinline__ float fc_dot(const float* __restrict__ W, const float* in_s,
                                        int j, int kq) {
    const float4* w4 = reinterpret_cast<const float4*>(W + (size_t)j * D + kq * 64);
    const float4* s4 = reinterpret_cast<const float4*>(in_s + kq * 64);
    float a0 = 0.0f, a1 = 0.0f, a2 = 0.0f, a3 = 0.0f;
#pragma unroll
    for (int i = 0; i < 16; i += 4) {
        a0 += dot4(w4[i], s4[i]);
        a1 += dot4(w4[i + 1], s4[i + 1]);
        a2 += dot4(w4[i + 2], s4[i + 2]);
        a3 += dot4(w4[i + 3], s4[i + 3]);
    }
    float v = (a0 + a1) + (a2 + a3);
    v += __shfl_xor_sync(0xffffffffu, v, 1);
    v += __shfl_xor_sync(0xffffffffu, v, 2);
    return v;
}

// full 256-dot per thread (4-way MLP)
__device__ __forceinline__ float dot256(const float* __restrict__ W, const float* in_s) {
    const float4* w4 = reinterpret_cast<const float4*>(W);
    const float4* s4 = reinterpret_cast<const float4*>(in_s);
    float a0 = 0.0f, a1 = 0.0f, a2 = 0.0f, a3 = 0.0f;
#pragma unroll 4
    for (int i = 0; i < 64; i += 4) {
        a0 += dot4(w4[i], s4[i]);
        a1 += dot4(w4[i + 1], s4[i + 1]);
        a2 += dot4(w4[i + 2], s4[i + 2]);
        a3 += dot4(w4[i + 3], s4[i + 3]);
    }
    return (a0 + a1) + (a2 + a3);
}

// LN(src[0..255]) -> dst, for 1024-thread blocks (t<256 active); all threads call.
__device__ __forceinline__ void ln256_1024(const float* src, float* dst,
                                           const float* __restrict__ g,
                                           const float* __restrict__ be, float* red) {
    const int t = threadIdx.x;
    const float sv = (t < D) ? src[t] : 0.0f;
    const float m = block_sum1024(sv, red) * (1.0f / (float)D);
    const float dv = sv - m;
    const float var = block_sum1024((t < D) ? dv * dv : 0.0f, red) * (1.0f / (float)D);
    const float rstd = rsqrtf(var + LN_EPS);
    if (t < D) dst[t] = dv * rstd * g[t] + be[t];
    __syncthreads();
}

// q = Wq@s + bq ; qk = SCALE * q @ WkT ; cn = SCALE * q.bk   (1024-thread block, slot n)
__device__ __forceinline__ void q_qk_1024(int n, const float* s_s, float* q_s,
                                          const float* __restrict__ Wq, const float* __restrict__ bq,
                                          const float* __restrict__ bk, float* red) {
    const int t = threadIdx.x;
    const int j = t >> 2, kq = t & 3;
    const float qv = fc_dot(Wq, s_s, j, kq);
    if (kq == 0) q_s[j] = qv + bq[j];
    __syncthreads();
    const float kv = fc_dot(g_WkT, q_s, j, kq);
    if (kq == 0) g_qk[n * D + j] = kv * SCALE;
    const float p = block_sum1024((t < D) ? q_s[t] * bk[t] : 0.0f, red);
    if (t == 0) g_cn[n] = p * SCALE;
}

// ---------------- K: materialize LN(x) once ----------------
__global__ void __launch_bounds__(256)
k_lnx(const float* __restrict__ x,
      const float* __restrict__ gin, const float* __restrict__ bin) {
    const int lane = threadIdx.x & 31;
    const int warp = threadIdx.x >> 5;
    const float4* gin4 = reinterpret_cast<const float4*>(gin);
    const float4* bin4 = reinterpret_cast<const float4*>(bin);
    const float4 gv0 = gin4[lane], gv1 = gin4[lane + 32];
    const float4 bb0 = bin4[lane], bb1 = bin4[lane + 32];

    const float4* x4 = reinterpret_cast<const float4*>(x);
    float4* o4 = reinterpret_cast<float4*>(g_xln);
    const int gw = blockIdx.x * 8 + warp;

    for (int r = gw; r < B_ROWS; r += 1024 * 8) {
        const float4 v0 = x4[(size_t)r * 64 + lane];
        const float4 v1 = x4[(size_t)r * 64 + 32 + lane];
        float sm = v0.x + v0.y + v0.z + v0.w + v1.x + v1.y + v1.z + v1.w;
        float sq = v0.x * v0.x + v0.y * v0.y + v0.z * v0.z + v0.w * v0.w
                 + v1.x * v1.x + v1.y * v1.y + v1.z * v1.z + v1.w * v1.w;
        sm = warp_sum(sm);
        sq = warp_sum(sq);
        const float mean = sm * (1.0f / 256.0f);
        const float var = fmaxf(sq * (1.0f / 256.0f) - mean * mean, 0.0f);
        const float rstd = rsqrtf(var + LN_EPS);
        float4 w0, w1;
        w0.x = (v0.x - mean) * rstd * gv0.x + bb0.x;
        w0.y = (v0.y - mean) * rstd * gv0.y + bb0.y;
        w0.z = (v0.z - mean) * rstd * gv0.z + bb0.z;
        w0.w = (v0.w - mean) * rstd * gv0.w + bb0.w;
        w1.x = (v1.x - mean) * rstd * gv1.x + bb1.x;
        w1.y = (v1.y - mean) * rstd * gv1.y + bb1.y;
        w1.z = (v1.z - mean) * rstd * gv1.z + bb1.z;
        w1.w = (v1.w - mean) * rstd * gv1.w + bb1.w;
        o4[(size_t)r * 64 + lane] = w0;
        o4[(size_t)r * 64 + 32 + lane] = w1;
    }
}

// ---------------- K: transpose Wk (once) ----------------
__global__ void k_wkT(const float* __restrict__ Wk) {
    __shared__ float tile[32][33];
    const int tx = threadIdx.x, ty = threadIdx.y;
    const int xi = blockIdx.x * 32 + tx;
#pragma unroll
    for (int r = 0; r < 32; r += 8)
        tile[ty + r][tx] = Wk[(size_t)(blockIdx.y * 32 + ty + r) * D + xi];
    __syncthreads();
    const int xo = blockIdx.y * 32 + tx;
#pragma unroll
    for (int r = 0; r < 32; r += 8)
        g_WkT[(size_t)(blockIdx.x * 32 + ty + r) * D + xo] = tile[tx][ty + r];
}

// ---------------- K: slots init + LN + q + qk (grid=NS, block=1024) ----------------
__global__ void __launch_bounds__(1024)
k_init(const float* __restrict__ noise, const float* __restrict__ mu,
       const float* __restrict__ sigma,
       const float* __restrict__ Wq, const float* __restrict__ bq,
       const float* __restrict__ bk,
       const float* __restrict__ gs, const float* __restrict__ bes) {
    __shared__ __align__(16) float h_s[D];
    __shared__ __align__(16) float s_s[D];
    __shared__ __align__(16) float q_s[D];
    __shared__ float red[32];
    const int n = blockIdx.x, t = threadIdx.x;

    if (t < D) {
        const float sv = mu[t] + sigma[t] * noise[n * D + t];
        g_slots[n * D + t] = sv;
        h_s[t] = sv;
    }
    __syncthreads();
    ln256_1024(h_s, s_s, gs, bes, red);
    q_qk_1024(n, s_s, q_s, Wq, bq, bk, red);
}

// ---------------- K_main: dots + softmax + accumulate (fused) ----------------
__global__ void __launch_bounds__(256, 1)
k_main() {
    __shared__ __align__(16) float qk_s[NS * D];
    __shared__ float cn_s[NS];
    __shared__ __align__(16) float ublk[NS * D];
    __shared__ float sblk[8][NS];

    const int tid = threadIdx.x;
    const int lane = tid & 31;
    const int warp = tid >> 5;

    for (int i = tid; i < NS * D; i += 256) qk_s[i] = g_qk[i];
    if (tid < NS) cn_s[tid] = g_cn[tid];
    __syncthreads();
    const int sigma = __brev((unsigned)(lane & 15)) >> 28;  // slot owned by this lane
    const float cn_r = cn_s[sigma];

    ull u2[NS][4];
#pragma unroll
    for (int n = 0; n < NS; n++)
#pragma unroll
        for (int p = 0; p < 4; p++) u2[n][p] = 0ull;
    float s_acc[NS];
#pragma unroll
    for (int n = 0; n < NS; n++) s_acc[n] = 0.0f;

    const float4* x4 = reinterpret_cast<const float4*>(g_xln);
    const float4* qk4 = reinterpret_cast<const float4*>(qk_s);
    int r = blockIdx.x * 8 + warp;

    float4 v0 = x4[(size_t)r * 64 + lane];
    float4 v1 = x4[(size_t)r * 64 + 32 + lane];

    while (true) {
        const int rn = r + TOTW_MAIN;
        const bool more = rn < B_ROWS;
        const size_t rl = more ? (size_t)rn : (size_t)r;
        const float4 p0 = x4[rl * 64 + lane];
        const float4 p1 = x4[rl * 64 + 32 + lane];

        const ull xl0 = pack2(v0.x, v0.y), xl1 = pack2(v0.z, v0.w);
        const ull xl2 = pack2(v1.x, v1.y), xl3 = pack2(v1.z, v1.w);

        // ---- 16 dots, lane-partial ----
        float d[NS];
#pragma unroll
        for (int n = 0; n < NS; n++) {
            const float4 qa = qk4[n * 64 + lane];
            const float4 qb = qk4[n * 64 + 32 + lane];
            ull acc = 0ull;
            fma2(acc, pack2(qa.x, qa.y), xl0);
            fma2(acc, pack2(qa.z, qa.w), xl1);
            fma2(acc, pack2(qb.x, qb.y), xl2);
            fma2(acc, pack2(qb.z, qb.w), xl3);
            float lo, hi;
            unpack2(acc, lo, hi);
            d[n] = lo + hi;
        }

        // ---- halving butterfly: lane l ends with full sum of slot bitrev4(l&15) ----
#pragma unroll
        for (int i = 0; i < 8; i++) {
            const float sent = (lane & 1) ? d[i] : d[i + 8];
            const float recv = __shfl_xor_sync(0xffffffffu, sent, 1);
            d[i] = (lane & 1) ? d[i + 8] + recv : d[i] + recv;
        }
#pragma unroll
        for (int i = 0; i < 4; i++) {
            const float sent = (lane & 2) ? d[i] : d[i + 4];
            const float recv = __shfl_xor_sync(0xffffffffu, sent, 2);
            d[i] = (lane & 2) ? d[i + 4] + recv : d[i] + recv;
        }
#pragma unroll
        for (int i = 0; i < 2; i++) {
            const float sent = (lane & 4) ? d[i] : d[i + 2];
            const float recv = __shfl_xor_sync(0xffffffffu, sent, 4);
            d[i] = (lane & 4) ? d[i + 2] + recv : d[i] + recv;
        }
        {
            const float sent = (lane & 8) ? d[0] : d[1];
            const float recv = __shfl_xor_sync(0xffffffffu, sent, 8);
            d[0] = (lane & 8) ? d[1] + recv : d[0] + recv;
        }
        d[0] += __shfl_xor_sync(0xffffffffu, d[0], 16);
        const float dd = d[0] + cn_r;

        // ---- softmax across the 16 slots (slot values live one per lane, 16-group) ----
        float mx = dd;
        mx = fmaxf(mx, __shfl_xor_sync(0xffffffffu, mx, 1));
        mx = fmaxf(mx, __shfl_xor_sync(0xffffffffu, mx, 2));
        mx = fmaxf(mx, __shfl_xor_sync(0xffffffffu, mx, 4));
        mx = fmaxf(mx, __shfl_xor_sync(0xffffffffu, mx, 8));
        const float e = __expf(dd - mx);
        float ssum = e;
        ssum += __shfl_xor_sync(0xffffffffu, ssum, 1);
        ssum += __shfl_xor_sync(0xffffffffu, ssum, 2);
        ssum += __shfl_xor_sync(0xffffffffu, ssum, 4);
        ssum += __shfl_xor_sync(0xffffffffu, ssum, 8);
        const float a = __fdividef(e, ssum) + ATT_EPS;

        // ---- redistribute: every lane needs all 16 attn values ----
        float av[NS];
#pragma unroll
        for (int n = 0; n < NS; n++) {
            const int src = ((n & 1) << 3) | ((n & 2) << 1) | ((n & 4) >> 1) | ((n & 8) >> 3);
            av[n] = __shfl_sync(0xffffffffu, a, src);
        }

        // ---- accumulate U (packed) and S ----
#pragma unroll
        for (int n = 0; n < NS; n++) {
            s_acc[n] += av[n];
            const ull a2 = pack2(av[n], av[n]);
            fma2(u2[n][0], a2, xl0);
            fma2(u2[n][1], a2, xl1);
            fma2(u2[n][2], a2, xl2);
            fma2(u2[n][3], a2, xl3);
        }

        if (!more) break;
        r = rn;
        v0 = p0;
        v1 = p1;
    }

    // stage per-warp partials into shared (serialized, deterministic)
    for (int w = 0; w < 8; w++) {
        if (warp == w) {
#pragma unroll
            for (int n = 0; n < NS; n++) {
#pragma unroll
                for (int p = 0; p < 4; p++) {
                    float lo, hi;
                    unpack2(u2[n][p], lo, hi);
                    const int c = (p < 2) ? (lane * 4 + 2 * p) : (128 + lane * 4 + 2 * (p - 2));
                    if (w == 0) {
                        ublk[n * D + c] = lo;
                        ublk[n * D + c + 1] = hi;
                    } else {
                        ublk[n * D + c] += lo;
                        ublk[n * D + c + 1] += hi;
                    }
                }
            }
            if (lane == 0) {
#pragma unroll
                for (int n = 0; n < NS; n++) sblk[w][n] = s_acc[n];
            }
        }
        __syncthreads();
    }

    for (int i = tid; i < NS * D; i += 256)
        g_partU[(size_t)blockIdx.x * (NS * D) + i] = ublk[i];
    if (tid < NS) {
        float t = 0.0f;
#pragma unroll
        for (int w = 0; w < 8; w++) t += sblk[w][tid];
        g_partS[blockIdx.x * NS + tid] = t;
    }
}

// ---------------- K_slot: entire slot chain, one block (1024 thr) per slot ----------------
__global__ void __launch_bounds__(1024)
k_slot(const float* __restrict__ Wv, const float* __restrict__ bv,
       const float* __restrict__ W_ih, const float* __restrict__ W_hh,
       const float* __restrict__ b_ih, const float* __restrict__ b_hh,
       const float* __restrict__ W1, const float* __restrict__ b1,
       const float* __restrict__ W2, const float* __restrict__ b2,
       const float* __restrict__ gf, const float* __restrict__ bef,
       const float* __restrict__ Wq, const float* __restrict__ bq,
       const float* __restrict__ bk,
       const float* __restrict__ gs, const float* __restrict__ bes,
       float* __restrict__ out, int write_out, int do_prep) {
    __shared__ __align__(16) float un_s[D];
    __shared__ __align__(16) float h_s[D];
    __shared__ __align__(16) float upd_s[D];
    __shared__ __align__(16) float gx_s[3 * D];
    __shared__ __align__(16) float gh_s[3 * D];
    __shared__ __align__(16) float hnew_s[D];
    __shared__ __align__(16) float vec_s[D];   // lnf, then hd, then s, then q (staged)
    __shared__ __align__(16) float vec2_s[D];
    __shared__ float red[32];
    __shared__ float S_sh;

    const int n = blockIdx.x, t = threadIdx.x;
    const int j = t >> 2, kq = t & 3;

    // ---- Stage A: reduce partials (U: 4 threads/col, 37 each; S: 148 threads) ----
    {
        float a = 0.0f;
        const int base = kq * 37;
#pragma unroll 4
        for (int i = 0; i < 37; i++)
            a += g_partU[(size_t)(base + i) * (NS * D) + n * D + j];
        a += __shfl_xor_sync(0xffffffffu, a, 1);
        a += __shfl_xor_sync(0xffffffffu, a, 2);
        if (kq == 0) un_s[j] = a;
        if (t < D) h_s[t] = g_slots[n * D + t];
        const float sv = (t < GRID_MAIN) ? g_partS[t * NS + n] : 0.0f;
        const float S = block_sum1024(sv, red);  // includes syncs -> un_s/h_s visible
        if (t == 0) S_sh = S;
        __syncthreads();
    }

    // ---- Stage B: updates = Wv @ (U/S) + bv ----
    {
        const float v = fc_dot(Wv, un_s, j, kq);
        if (kq == 0) upd_s[j] = v / S_sh + bv[j];
        __syncthreads();
    }

    // ---- Stage C: GRU gates (6 x 256 dots over 1024 threads, 1.5 passes) ----
    {
        const int jj = t & 255;
        const int gg = t >> 8;
        {
            const float* W = (gg < 3) ? (W_ih + (size_t)(gg * D + jj) * D)
                                      : (W_hh + (size_t)jj * D);
            const float* in = (gg < 3) ? upd_s : h_s;
            const float acc = dot256(W, in);
            if (gg < 3) gx_s[gg * D + jj] = acc + b_ih[gg * D + jj];
            else gh_s[jj] = acc + b_hh[jj];
        }
        if (gg < 2) {
            const float acc = dot256(W_hh + (size_t)((gg + 1) * D + jj) * D, h_s);
            gh_s[(gg + 1) * D + jj] = acc + b_hh[(gg + 1) * D + jj];
        }
        __syncthreads();
    }

    // ---- Stage D: GRU combine + LN -> vec_s (lnf) ----
    if (t < D) {
        const float r = sigmoidf_(gx_s[t] + gh_s[t]);
        const float z = sigmoidf_(gx_s[D + t] + gh_s[D + t]);
        const float nn = tanhf(gx_s[2 * D + t] + r * gh_s[2 * D + t]);
        hnew_s[t] = (1.0f - z) * nn + z * h_s[t];
    }
    __syncthreads();
    ln256_1024(hnew_s, vec_s, gf, bef, red);

    // ---- Stage E: hidden = relu(W1 @ lnf + b1) -> vec2_s ----
    {
        const float v = fc_dot(W1, vec_s, j, kq);
        if (kq == 0) vec2_s[j] = fmaxf(v + b1[j], 0.0f);
        __syncthreads();
    }

    // ---- Stage F: res = hnew + W2 @ hidden + b2 -> slots ----
    {
        const float v = fc_dot(W2, vec2_s, j, kq);
        if (kq == 0) {
            const float res = hnew_s[j] + v + b2[j];
            un_s[j] = res;  // reuse un_s as res buffer
            g_slots[n * D + j] = res;
            if (write_out) out[n * D + j] = res;
        }
        __syncthreads();
    }

    if (!do_prep) return;

    // ---- Stage G/H/I: LN(res) -> q -> qk, cn (for next iteration) ----
    ln256_1024(un_s, vec_s, gs, bes, red);
    q_qk_1024(n, vec_s, vec2_s, Wq, bq, bk, red);
}

// ---------------- launch ----------------
extern "C" void kernel_launch(void* const* d_in, const int* in_sizes, int n_in,
                              void* d_out, int out_size) {
    const float* x      = (const float*)d_in[0];
    const float* noise  = (const float*)d_in[1];
    const float* mu     = (const float*)d_in[2];
    const float* sigma  = (const float*)d_in[3];
    const float* Wq     = (const float*)d_in[4];
    const float* bq     = (const float*)d_in[5];
    const float* Wk     = (const float*)d_in[6];
    const float* bk     = (const float*)d_in[7];
    const float* Wv     = (const float*)d_in[8];
    const float* bv     = (const float*)d_in[9];
    const float* W_ih   = (const float*)d_in[10];
    const float* W_hh   = (const float*)d_in[11];
    const float* b_ih   = (const float*)d_in[12];
    const float* b_hh   = (const float*)d_in[13];
    const float* W1     = (const float*)d_in[14];
    const float* b1     = (const float*)d_in[15];
    const float* W2     = (const float*)d_in[16];
    const float* b2     = (const float*)d_in[17];
    const float* g_in   = (const float*)d_in[18];
    const float* be_in  = (const float*)d_in[19];
    const float* g_s    = (const float*)d_in[20];
    const float* be_s   = (const float*)d_in[21];
    const float* g_f    = (const float*)d_in[22];
    const float* be_f   = (const float*)d_in[23];
    float* out = (float*)d_out;

    k_lnx<<<1024, 256>>>(x, g_in, be_in);
    k_wkT<<<dim3(8, 8), dim3(32, 8)>>>(Wk);
    k_init<<<NS, 1024>>>(noise, mu, sigma, Wq, bq, bk, g_s, be_s);

    for (int it = 0; it < 3; it++) {
        k_main<<<GRID_MAIN, 256>>>();
        k_slot<<<NS, 1024>>>(Wv, bv, W_ih, W_hh, b_ih, b_hh, W1, b1, W2, b2,
                             g_f, be_f, Wq, bq, bk, g_s, be_s,
                             out, it == 2 ? 1 : 0, it == 2 ? 0 : 1);
    }
}